// round 6
// baseline (speedup 1.0000x reference)
#include <cuda_runtime.h>

// Problem constants
#define Bn 2
#define Cn 32
#define INV8 0.3535533905932738f   // 1/(2*sqrt(2))
#define NVOXH 110592               // 48^3
#define NBN 221184                 // 2 * 48^3

// Scratch (static device globals; no allocations allowed)
__device__ float g_S[Bn * Cn * 8];          // parity-class sums per (b,c)
__device__ float g_W2[Bn][Cn][8][Cn];       // [b][c][corner][o] folded weights
__device__ float g_sum[Cn];
__device__ float g_sq[Cn];

// ---------------------------------------------------------------------------
__global__ void k_zero() {
    int t = threadIdx.x;
    if (t < Bn * Cn * 8) g_S[t] = 0.f;
    if (t < Cn) { g_sum[t] = 0.f; g_sq[t] = 0.f; }
}

// ---------------------------------------------------------------------------
// Parity-class sums: S[b][c][pd*4+ph*2+pw] = sum of x over voxels with those
// parities. One (b,c) volume = 884736 floats = 221184 float4, split in 16 slabs.
__global__ void k_parity(const float4* __restrict__ x4) {
    int bc = blockIdx.y;                 // 0..63
    int slab = blockIdx.x;               // 0..15
    const float4* p = x4 + (size_t)bc * 221184 + (size_t)slab * 13824;
    float a[8];
#pragma unroll
    for (int j = 0; j < 8; j++) a[j] = 0.f;
    for (int i = threadIdx.x; i < 13824; i += 256) {
        int f = slab * 13824 + i;        // global float4 index in (b,c) volume
        int h = (f / 24) % 96;           // 24 float4 per W-row
        int d = f / 2304;                // 2304 float4 per D-slice
        int cls = ((d & 1) * 2 + (h & 1)) * 2;
        float4 v = p[i];
        a[cls]     += v.x + v.z;         // even-w
        a[cls + 1] += v.y + v.w;         // odd-w
    }
#pragma unroll
    for (int j = 0; j < 8; j++) {
        for (int s = 16; s > 0; s >>= 1)
            a[j] += __shfl_xor_sync(0xffffffffu, a[j], s);
    }
    if ((threadIdx.x & 31) == 0) {
#pragma unroll
        for (int j = 0; j < 8; j++) atomicAdd(&g_S[bc * 8 + j], a[j]);
    }
}

// ---------------------------------------------------------------------------
// Band means -> channel attention MLPs -> sigmoid scales -> folded W2 weights.
// band index = sd*4 + sh*2 + sw ; band 0 = aaa(low), bands 1..7 map to
// [aad,ada,add,daa,dad,dda,ddd] (z channel = 32 + c*7 + band-1).
__global__ void k_attn(const float* __restrict__ w1_low, const float* __restrict__ w2_low,
                       const float* __restrict__ w1_high, const float* __restrict__ w2_high,
                       const float* __restrict__ w_fuse) {
    __shared__ float mean8[Bn][Cn][8];
    __shared__ float hl[Bn][2];
    __shared__ float hh[Bn][14];
    __shared__ float s_all[Bn][256];
    int tid = threadIdx.x;

    if (tid < Bn * Cn) {
        int b = tid >> 5, c = tid & 31;
        float S[8];
#pragma unroll
        for (int p = 0; p < 8; p++) S[p] = g_S[tid * 8 + p];
#pragma unroll
        for (int band = 0; band < 8; band++) {
            float m = 0.f;
#pragma unroll
            for (int p = 0; p < 8; p++)
                m += (__popc(band & p) & 1) ? -S[p] : S[p];
            mean8[b][c][band] = m * (INV8 / 110592.f);
        }
    }
    __syncthreads();

    if (tid < 4) {                       // low hidden: (B,2)
        int b = tid >> 1, r = tid & 1;
        float h = 0.f;
        for (int c = 0; c < 32; c++) h += mean8[b][c][0] * w1_low[r * 32 + c];
        hl[b][r] = fmaxf(h, 0.f);
    } else if (tid < 32) {               // high hidden: (B,14)
        int idx = tid - 4;
        int b = idx / 14, r = idx % 14;
        float h = 0.f;
        for (int j = 0; j < 224; j++)
            h += mean8[b][j / 7][1 + j % 7] * w1_high[r * 224 + j];
        hh[b][r] = fmaxf(h, 0.f);
    }
    __syncthreads();

    for (int t = tid; t < 512; t += 256) {   // sigmoid scales, 2*256
        int b = t >> 8, ch = t & 255;
        float pre = 0.f;
        if (ch < 32) {
            for (int r = 0; r < 2; r++) pre += hl[b][r] * w2_low[ch * 2 + r];
        } else {
            int j = ch - 32;
            for (int r = 0; r < 14; r++) pre += hh[b][r] * w2_high[j * 14 + r];
        }
        s_all[b][ch] = 1.f / (1.f + expf(-pre));
    }
    __syncthreads();

    // W2[b][c][corner][o] = INV8 * sum_band sign(band,corner)*w_fuse[o,ch]*s[b,ch]
    for (int t = tid; t < 16384; t += 256) {
        int b = t >> 13;
        int c = (t >> 8) & 31;
        int corner = (t >> 5) & 7;
        int o = t & 31;
        float val = w_fuse[o * 256 + c] * s_all[b][c];   // band 0 (aaa), sign +1
#pragma unroll
        for (int band = 1; band < 8; band++) {
            int ch = 32 + c * 7 + band - 1;
            float term = w_fuse[o * 256 + ch] * s_all[b][ch];
            val += (__popc(band & corner) & 1) ? -term : term;
        }
        g_W2[b][c][corner][o] = val * INV8;
    }
}

// ---------------------------------------------------------------------------
// Packed fp32x2 helpers (Blackwell FFMA2 — only reachable via PTX)
__device__ __forceinline__ unsigned long long fma2(unsigned long long a,
                                                   unsigned long long b,
                                                   unsigned long long c) {
    unsigned long long d;
    asm("fma.rn.f32x2 %0, %1, %2, %3;" : "=l"(d) : "l"(a), "l"(b), "l"(c));
    return d;
}
__device__ __forceinline__ unsigned long long pack2(float lo, float hi) {
    unsigned long long r;
    asm("mov.b64 %0, {%1, %2};" : "=l"(r) : "f"(lo), "f"(hi));
    return r;
}
__device__ __forceinline__ void unpack2(unsigned long long v, float& lo, float& hi) {
    asm("mov.b64 {%0, %1}, %2;" : "=f"(lo), "=f"(hi) : "l"(v));
}

// ---------------------------------------------------------------------------
// Fused stride-2 2x2x2 conv: out_pre[b,o,p] = sum_{c,corner} W2 * x + b_fuse[o].
// Each thread computes 2 adjacent output-W points (input = one float4 per row),
// all 32 output channels as 16 fp32x2 accumulators (pair = two o-channels).
__global__ void __launch_bounds__(256) k_conv(const float* __restrict__ x,
                                              const float* __restrict__ b_fuse,
                                              float* __restrict__ out) {
    __shared__ float sw[Cn * 8 * Cn];    // 32 KB: [c][corner][o]
    __shared__ float sb[Cn];
    int tid = threadIdx.x;
    int b = blockIdx.y;
    const float* wsrc = &g_W2[b][0][0][0];
    for (int t = tid; t < 8192; t += 256) sw[t] = wsrc[t];
    if (tid < 32) sb[tid] = b_fuse[tid];
    __syncthreads();

    int P = blockIdx.x * 256 + tid;      // 0..55295 (point-pair index)
    int t24 = P % 24;                    // output-W pair (w = 2*t24, 2*t24+1)
    int h = (P / 24) % 48;
    int d = P / 1152;

    const float4* xb = (const float4*)x;
    size_t base = (((size_t)(b * 32) * 96 + 2 * d) * 96 + 2 * h) * 24 + t24;
    const unsigned long long* swq = (const unsigned long long*)sw;

    unsigned long long accA[16], accB[16];
#pragma unroll
    for (int i = 0; i < 16; i++) { accA[i] = 0ull; accB[i] = 0ull; }

#pragma unroll 4
    for (int c = 0; c < 32; c++) {
        const float4* p = xb + base + (size_t)c * 221184;
        float4 r00 = p[0];       // (i=0,j=0)
        float4 r01 = p[24];      // (i=0,j=1)
        float4 r10 = p[2304];    // (i=1,j=0)
        float4 r11 = p[2328];    // (i=1,j=1)
        float xA[8], xB[8];      // corner = i*4 + j*2 + k
        xA[0] = r00.x; xB[0] = r00.z;  xA[1] = r00.y; xB[1] = r00.w;
        xA[2] = r01.x; xB[2] = r01.z;  xA[3] = r01.y; xB[3] = r01.w;
        xA[4] = r10.x; xB[4] = r10.z;  xA[5] = r10.y; xB[5] = r10.w;
        xA[6] = r11.x; xB[6] = r11.z;  xA[7] = r11.y; xB[7] = r11.w;
#pragma unroll
        for (int corner = 0; corner < 8; corner++) {
            unsigned long long a2 = pack2(xA[corner], xA[corner]);
            unsigned long long b2 = pack2(xB[corner], xB[corner]);
            const unsigned long long* wq = swq + (c * 8 + corner) * 16;
#pragma unroll
            for (int op = 0; op < 16; op++) {
                unsigned long long w = wq[op];         // {w[2op], w[2op+1]} broadcast LDS.64
                accA[op] = fma2(w, a2, accA[op]);
                accB[op] = fma2(w, b2, accB[op]);
            }
        }
    }

    // coalesced float2 stores: two adjacent output-W points per channel
    size_t obase2 = (size_t)(b * 32) * 55296 + (size_t)d * 1152 + (size_t)h * 24 + t24;
    float2* o2 = (float2*)out;
#pragma unroll
    for (int op = 0; op < 16; op++) {
        float a0, a1, b0, b1;
        unpack2(accA[op], a0, a1);
        unpack2(accB[op], b0, b1);
        float bias0 = sb[2 * op], bias1 = sb[2 * op + 1];
        float2 v0; v0.x = a0 + bias0; v0.y = b0 + bias0;
        float2 v1; v1.x = a1 + bias1; v1.y = b1 + bias1;
        o2[obase2 + (size_t)(2 * op) * 55296] = v0;
        o2[obase2 + (size_t)(2 * op + 1) * 55296] = v1;
    }
}

// ---------------------------------------------------------------------------
// Per-output-channel sum / sumsq over (B, spatial) for BatchNorm.
__global__ void k_stats(const float* __restrict__ z) {
    int bo = blockIdx.y;                 // 0..63 ; channel = bo & 31
    int o = bo & 31;
    const float4* p = (const float4*)(z + (size_t)bo * 110592) + (size_t)blockIdx.x * 1024;
    float s = 0.f, q = 0.f;
    for (int k = threadIdx.x; k < 1024; k += 256) {
        float4 v = p[k];
        s += v.x + v.y + v.z + v.w;
        q += v.x * v.x + v.y * v.y + v.z * v.z + v.w * v.w;
    }
    for (int sh = 16; sh > 0; sh >>= 1) {
        s += __shfl_xor_sync(0xffffffffu, s, sh);
        q += __shfl_xor_sync(0xffffffffu, q, sh);
    }
    __shared__ float ws[8][2];
    int w = threadIdx.x >> 5;
    if ((threadIdx.x & 31) == 0) { ws[w][0] = s; ws[w][1] = q; }
    __syncthreads();
    if (threadIdx.x == 0) {
        float S = 0.f, Q = 0.f;
        for (int i = 0; i < 8; i++) { S += ws[i][0]; Q += ws[i][1]; }
        atomicAdd(&g_sum[o], S);
        atomicAdd(&g_sq[o], Q);
    }
}

// ---------------------------------------------------------------------------
// In-place BatchNorm (batch stats) + affine + ReLU.
__global__ void k_final(float* __restrict__ z, const float* __restrict__ gamma,
                        const float* __restrict__ beta) {
    int idx = blockIdx.x * 256 + threadIdx.x;   // float4 index, total 1769472
    int o = (idx / 27648) & 31;                 // 27648 float4 per (b,o) plane
    float mu = g_sum[o] * (1.f / (float)NBN);
    float var = g_sq[o] * (1.f / (float)NBN) - mu * mu;
    float inv = rsqrtf(var + 1e-5f);
    float sc = gamma[o] * inv;
    float sh = beta[o] - mu * sc;
    float4* p = (float4*)z;
    float4 v = p[idx];
    v.x = fmaxf(v.x * sc + sh, 0.f);
    v.y = fmaxf(v.y * sc + sh, 0.f);
    v.z = fmaxf(v.z * sc + sh, 0.f);
    v.w = fmaxf(v.w * sc + sh, 0.f);
    p[idx] = v;
}

// ---------------------------------------------------------------------------
extern "C" void kernel_launch(void* const* d_in, const int* in_sizes, int n_in,
                              void* d_out, int out_size) {
    const float* x       = (const float*)d_in[0];
    const float* w1_low  = (const float*)d_in[1];
    const float* w2_low  = (const float*)d_in[2];
    const float* w1_high = (const float*)d_in[3];
    const float* w2_high = (const float*)d_in[4];
    const float* w_fuse  = (const float*)d_in[5];
    const float* b_fuse  = (const float*)d_in[6];
    const float* gamma   = (const float*)d_in[7];
    const float* beta    = (const float*)d_in[8];
    float* out = (float*)d_out;

    k_zero<<<1, 512>>>();
    k_parity<<<dim3(16, 64), 256>>>((const float4*)x);
    k_attn<<<1, 256>>>(w1_low, w2_low, w1_high, w2_high, w_fuse);
    k_conv<<<dim3(216, 2), 256>>>(x, b_fuse, out);
    k_stats<<<dim3(27, 64), 256>>>(out);
    k_final<<<6912, 256>>>(out, gamma, beta);
}